// round 10
// baseline (speedup 1.0000x reference)
#include <cuda_runtime.h>

#define B 8
#define CIN 16
#define COUT 32
#define EDGES 120000
#define NTOT (B * EDGES)            // 960000
#define BN_EPS 1e-5f

#define CHUNK 96                    // edges per block; 120000 % 96 == 0
#define NROWS (CHUNK * 5)           // 480 staged rows per block
#define SLOT_PAD 97                 // slot-dim pad: bank-spread, conflict-free reads

typedef unsigned long long u64;

// Scratch: transposed x [B*E, CIN] (61.4 MB) + BN stat accumulators.
__device__ float g_xT[(size_t)NTOT * CIN];
__device__ float g_sum[COUT];
__device__ float g_sumsq[COUT];

// ---- packed f32x2 helpers (sm_100+) ---------------------------------------
__device__ __forceinline__ u64 splat2(float f) {
    u64 r;
    asm("mov.b64 %0, {%1, %1};" : "=l"(r) : "f"(f));
    return r;
}
__device__ __forceinline__ void ffma2(u64& acc, u64 a, u64 b) {
    asm("fma.rn.f32x2 %0, %1, %2, %0;" : "+l"(acc) : "l"(a), "l"(b));
}
__device__ __forceinline__ void unpack2(u64 v, float& lo, float& hi) {
    asm("mov.b64 {%0, %1}, %2;" : "=f"(lo), "=f"(hi) : "l"(v));
}

// ---------------------------------------------------------------------------
// Kernel 1: transpose x [B, CIN, E] -> g_xT [B*E, CIN]; zero stat buffers.
// ---------------------------------------------------------------------------
__global__ __launch_bounds__(256) void transpose_kernel(const float* __restrict__ x) {
    int i = blockIdx.x * 256 + threadIdx.x;
    if (blockIdx.x == 0 && threadIdx.x < 2 * COUT) {
        if (threadIdx.x < COUT) g_sum[threadIdx.x] = 0.f;
        else                    g_sumsq[threadIdx.x - COUT] = 0.f;
    }
    if (i >= NTOT) return;
    int b = i / EDGES;
    int e = i - b * EDGES;
    const float* xb = x + (size_t)b * CIN * EDGES + e;
    float v[CIN];
#pragma unroll
    for (int c = 0; c < CIN; c++) v[c] = xb[(size_t)c * EDGES];
    float4* dst = (float4*)&g_xT[(size_t)i * CIN];
#pragma unroll
    for (int q = 0; q < 4; q++)
        dst[q] = make_float4(v[4 * q], v[4 * q + 1], v[4 * q + 2], v[4 * q + 3]);
}

// ---------------------------------------------------------------------------
// Kernel 2: mesh conv + bias -> d_out.
// Phase A: 480 rows (96 edges x 5) cooperatively gathered: 4 lanes fetch one
//          64B row in a single warp-instr -> 1 L1tex wavefront per row
//          (4x fewer than per-thread scattered gathers).
// Phase B: 1 edge per thread; features via conflict-free LDS.128 from the
//          staged [r][cc][slot] layout; weights via broadcast LDS.128;
//          channel-packed f32x2 MACs. ~80 regs -> 15 warps/SM; phase A of
//          some CTAs overlaps phase B of others.
// ---------------------------------------------------------------------------
__global__ __launch_bounds__(CHUNK) void conv_kernel(const int* __restrict__ gemm,
                                                     const float* __restrict__ W,
                                                     const float* __restrict__ bias,
                                                     float* __restrict__ out) {
    __shared__ __align__(16) float s_rows[5 * 4 * SLOT_PAD * 4]; // [(r*4+cc)*97+slot]*4
    __shared__ __align__(16) float s_W[CIN * 5 * COUT];          // [c*5+s][o]
    __shared__ __align__(16) float s_bias[COUT];
    __shared__ __align__(16) int   s_g[CHUNK * 4];

    int tid  = threadIdx.x;
    int base = blockIdx.x * CHUNK;

    for (int j = tid; j < CIN * 5 * COUT; j += CHUNK) {
        int cs = j >> 5;
        int o  = j & 31;
        s_W[j] = W[o * (CIN * 5) + cs];
    }
    if (tid < COUT) s_bias[tid] = bias[tid];
    ((int4*)s_g)[tid] = ((const int4*)gemm)[base + tid];
    __syncthreads();

    // ---- Phase A: cooperative row staging --------------------------------
    int p = tid & 3;                       // 16B piece of the 64B row
    for (int rid = tid >> 2; rid < NROWS; rid += CHUNK / 4) {
        int slot = rid / 5;
        int r    = rid - slot * 5;
        int gi   = base + slot;
        int bb   = gi / EDGES;
        int row  = (r == 0) ? gi : (bb * EDGES + s_g[slot * 4 + (r - 1)]);
        float4 v = *(const float4*)(g_xT + (size_t)row * CIN + p * 4);
        *(float4*)&s_rows[(((r << 2) + p) * SLOT_PAD + slot) * 4] = v;
    }
    __syncthreads();

    // ---- Phase B: per-edge MAC -------------------------------------------
    int slot = tid;
    int gi   = base + slot;
    int bb   = gi / EDGES;
    int e    = gi - bb * EDGES;

    u64 acc[COUT / 2];
    const u64* bias2 = (const u64*)s_bias;
#pragma unroll
    for (int q = 0; q < COUT / 2; q++) acc[q] = bias2[q];

#pragma unroll
    for (int cc = 0; cc < 4; cc++) {
        float4 vx = *(const float4*)&s_rows[((0 * 4 + cc) * SLOT_PAD + slot) * 4];
        float4 va = *(const float4*)&s_rows[((1 * 4 + cc) * SLOT_PAD + slot) * 4];
        float4 vb = *(const float4*)&s_rows[((2 * 4 + cc) * SLOT_PAD + slot) * 4];
        float4 vc = *(const float4*)&s_rows[((3 * 4 + cc) * SLOT_PAD + slot) * 4];
        float4 vd = *(const float4*)&s_rows[((4 * 4 + cc) * SLOT_PAD + slot) * 4];
#pragma unroll
        for (int j = 0; j < 4; j++) {
            int c = cc * 4 + j;
            float fa = (&va.x)[j], fb = (&vb.x)[j], fc = (&vc.x)[j], fd = (&vd.x)[j];
            float fv[5];
            fv[0] = (&vx.x)[j];
            fv[1] = fabsf(fa - fc);
            fv[2] = fa + fc;
            fv[3] = fabsf(fb - fd);
            fv[4] = fb + fd;
#pragma unroll
            for (int s = 0; s < 5; s++) {
                u64 f2 = splat2(fv[s]);
                const ulonglong2* wr = (const ulonglong2*)&s_W[(c * 5 + s) * COUT];
#pragma unroll
                for (int q = 0; q < 8; q++) {   // broadcast LDS.128 weights
                    ulonglong2 w2 = wr[q];
                    ffma2(acc[2 * q],     f2, w2.x);
                    ffma2(acc[2 * q + 1], f2, w2.y);
                }
            }
        }
    }

    float* ob = out + (size_t)bb * COUT * EDGES + e;
#pragma unroll
    for (int q = 0; q < COUT / 2; q++) {
        float lo, hi;
        unpack2(acc[q], lo, hi);
        ob[(size_t)(2 * q)     * EDGES] = lo;   // lanes e-contiguous -> coalesced
        ob[(size_t)(2 * q + 1) * EDGES] = hi;
    }
}

// ---------------------------------------------------------------------------
// Kernel 3: BN statistics. 4 chunk-blocks per (b, o) row (1024 blocks).
// ---------------------------------------------------------------------------
__global__ __launch_bounds__(256) void stats_kernel(const float* __restrict__ out) {
    __shared__ float s1[256];
    __shared__ float s2[256];
    int blk   = blockIdx.x;               // blk = (b*COUT + o) * 4 + chunk
    int row   = blk >> 2;
    int chunk = blk & 3;
    int o     = row & (COUT - 1);
    const int E4 = EDGES / 4;             // 30000 float4 per row
    const int C4 = E4 / 4;                // 7500 float4 per chunk
    const float4* rp = (const float4*)(out + (size_t)row * EDGES) + chunk * C4;

    float a1 = 0.f, a2 = 0.f;
    for (int j = threadIdx.x; j < C4; j += 256) {
        float4 v = rp[j];
        a1 += v.x + v.y + v.z + v.w;
        a2 += v.x * v.x + v.y * v.y + v.z * v.z + v.w * v.w;
    }
    s1[threadIdx.x] = a1;
    s2[threadIdx.x] = a2;
    __syncthreads();
#pragma unroll
    for (int st = 128; st > 0; st >>= 1) {
        if (threadIdx.x < st) {
            s1[threadIdx.x] += s1[threadIdx.x + st];
            s2[threadIdx.x] += s2[threadIdx.x + st];
        }
        __syncthreads();
    }
    if (threadIdx.x == 0) {
        atomicAdd(&g_sum[o],   s1[0]);
        atomicAdd(&g_sumsq[o], s2[0]);
    }
}

// ---------------------------------------------------------------------------
// Kernel 4: y -> relu(y*scale + shift), in place (finalize merged).
// ---------------------------------------------------------------------------
__global__ __launch_bounds__(256) void norm_relu_kernel(float* __restrict__ out,
                                                        const float* __restrict__ gamma,
                                                        const float* __restrict__ beta) {
    __shared__ float s_scale[COUT];
    __shared__ float s_shift[COUT];
    if (threadIdx.x < COUT) {
        int o = threadIdx.x;
        float inv  = 1.0f / (float)NTOT;
        float mean = g_sum[o] * inv;
        float var  = g_sumsq[o] * inv - mean * mean;
        float rstd = rsqrtf(var + BN_EPS);
        float sc   = gamma[o] * rstd;
        s_scale[o] = sc;
        s_shift[o] = beta[o] - mean * sc;
    }
    __syncthreads();

    int i = blockIdx.x * 256 + threadIdx.x;      // float4 index, exact grid
    const int E4 = EDGES / 4;
    int o = (i / E4) & (COUT - 1);
    float sc = s_scale[o];
    float sh = s_shift[o];
    float4 v = ((float4*)out)[i];
    v.x = fmaxf(fmaf(v.x, sc, sh), 0.f);
    v.y = fmaxf(fmaf(v.y, sc, sh), 0.f);
    v.z = fmaxf(fmaf(v.z, sc, sh), 0.f);
    v.w = fmaxf(fmaf(v.w, sc, sh), 0.f);
    ((float4*)out)[i] = v;
}

// ---------------------------------------------------------------------------
extern "C" void kernel_launch(void* const* d_in, const int* in_sizes, int n_in,
                              void* d_out, int out_size) {
    const float* x     = (const float*)d_in[0];
    const int*   gemm  = (const int*)  d_in[1];
    const float* W     = (const float*)d_in[2];
    const float* bias  = (const float*)d_in[3];
    const float* gamma = (const float*)d_in[4];
    const float* beta  = (const float*)d_in[5];
    float* out = (float*)d_out;

    transpose_kernel<<<NTOT / 256, 256>>>(x);
    conv_kernel<<<NTOT / CHUNK, CHUNK>>>(gemm, W, bias, out);
    stats_kernel<<<B * COUT * 4, 256>>>(out);
    norm_relu_kernel<<<(NTOT * COUT / 4) / 256, 256>>>(out, gamma, beta);
}

// round 13
// speedup vs baseline: 1.2757x; 1.2757x over previous
#include <cuda_runtime.h>

#define B 8
#define CIN 16
#define COUT 32
#define EDGES 120000
#define NTOT (B * EDGES)            // 960000
#define BN_EPS 1e-5f

typedef unsigned long long u64;

// Scratch: transposed x [B*E, CIN] (61.4 MB) + BN stat accumulators.
__device__ float g_xT[(size_t)NTOT * CIN];
__device__ float g_sum[COUT];
__device__ float g_sumsq[COUT];

// ---- packed f32x2 helpers (sm_100+) ---------------------------------------
__device__ __forceinline__ u64 splat2(float f) {
    u64 r;
    asm("mov.b64 %0, {%1, %1};" : "=l"(r) : "f"(f));
    return r;
}
__device__ __forceinline__ void ffma2(u64& acc, u64 a, u64 b) {
    asm("fma.rn.f32x2 %0, %1, %2, %0;" : "+l"(acc) : "l"(a), "l"(b));
}
__device__ __forceinline__ void unpack2(u64 v, float& lo, float& hi) {
    asm("mov.b64 {%0, %1}, %2;" : "=f"(lo), "=f"(hi) : "l"(v));
}

// ---------------------------------------------------------------------------
// Kernel 1: transpose x [B, CIN, E] -> g_xT [B*E, CIN]; zero stat buffers.
// ---------------------------------------------------------------------------
__global__ __launch_bounds__(256) void transpose_kernel(const float* __restrict__ x) {
    int i = blockIdx.x * 256 + threadIdx.x;
    if (blockIdx.x == 0 && threadIdx.x < 2 * COUT) {
        if (threadIdx.x < COUT) g_sum[threadIdx.x] = 0.f;
        else                    g_sumsq[threadIdx.x - COUT] = 0.f;
    }
    if (i >= NTOT) return;
    int b = i / EDGES;
    int e = i - b * EDGES;
    const float* xb = x + (size_t)b * CIN * EDGES + e;
    float v[CIN];
#pragma unroll
    for (int c = 0; c < CIN; c++) v[c] = xb[(size_t)c * EDGES];
    float4* dst = (float4*)&g_xT[(size_t)i * CIN];
#pragma unroll
    for (int q = 0; q < 4; q++)
        dst[q] = make_float4(v[4 * q], v[4 * q + 1], v[4 * q + 2], v[4 * q + 3]);
}

// ---------------------------------------------------------------------------
// Kernel 2: mesh conv + bias -> d_out.
// Lane-pair split: lanes 2k/2k+1 share the SAME 2 consecutive edges (gather
// addresses duplicate in pairs -> coalesced), each owns 16 of 32 channels.
// acc = 32 regs -> launch_bounds(128,4) -> 16 warps/SM (2x R8) so the FFMA2
// pipe (74us chip floor) overlaps LDS/gather latency instead of serializing.
// Weights via broadcast LDS.128 from smem (4 per cs per thread).
// ---------------------------------------------------------------------------
__global__ __launch_bounds__(128, 4) void conv_kernel(const int* __restrict__ gemm,
                                                      const float* __restrict__ W,
                                                      const float* __restrict__ bias,
                                                      float* __restrict__ out) {
    __shared__ __align__(16) float s_W[CIN * 5 * COUT];   // [c*5+s][o]
    __shared__ __align__(16) float s_bias[COUT];

    int tid = threadIdx.x;
    for (int j = tid; j < CIN * 5 * COUT; j += 128) {
        int cs = j >> 5;
        int o  = j & 31;
        s_W[j] = W[o * (CIN * 5) + cs];
    }
    if (tid < COUT) s_bias[tid] = bias[tid];
    __syncthreads();

    int pair = tid >> 1;                     // 64 pairs per block
    int half = tid & 1;                      // channel half: 0 -> ch 0..15, 1 -> ch 16..31
    int i0   = blockIdx.x * 128 + pair * 2;  // block covers 128 edges; grid exact
    int b    = i0 / EDGES;                   // EDGES even -> pair within one batch
    int e    = i0 - b * EDGES;
    size_t nb = (size_t)b * EDGES;

    int4 g0 = ((const int4*)gemm)[i0];
    int4 g1 = ((const int4*)gemm)[i0 + 1];
    const float4* x0 = (const float4*)&g_xT[(size_t)i0 * CIN];
    const float4* x1 = (const float4*)&g_xT[(size_t)(i0 + 1) * CIN];
    const float4* a0 = (const float4*)&g_xT[(nb + (size_t)g0.x) * CIN];
    const float4* b0 = (const float4*)&g_xT[(nb + (size_t)g0.y) * CIN];
    const float4* c0 = (const float4*)&g_xT[(nb + (size_t)g0.z) * CIN];
    const float4* d0 = (const float4*)&g_xT[(nb + (size_t)g0.w) * CIN];
    const float4* a1 = (const float4*)&g_xT[(nb + (size_t)g1.x) * CIN];
    const float4* b1 = (const float4*)&g_xT[(nb + (size_t)g1.y) * CIN];
    const float4* c1 = (const float4*)&g_xT[(nb + (size_t)g1.z) * CIN];
    const float4* d1 = (const float4*)&g_xT[(nb + (size_t)g1.w) * CIN];

    // acc[edge][p]: channels half*16 + 2p, 2p+1 (8 pairs = 16 channels).
    u64 acc0[8], acc1[8];
    const u64* bias2 = (const u64*)s_bias;
#pragma unroll
    for (int p = 0; p < 8; p++) { acc0[p] = bias2[half * 8 + p]; acc1[p] = bias2[half * 8 + p]; }

#pragma unroll
    for (int cc = 0; cc < 4; cc++) {
        float4 vx0 = x0[cc], va0 = a0[cc], vb0 = b0[cc], vc0 = c0[cc], vd0 = d0[cc];
        float4 vx1 = x1[cc], va1 = a1[cc], vb1 = b1[cc], vc1 = c1[cc], vd1 = d1[cc];
#pragma unroll
        for (int j = 0; j < 4; j++) {
            int c = cc * 4 + j;
            float fa0 = (&va0.x)[j], fb0 = (&vb0.x)[j], fc0 = (&vc0.x)[j], fd0 = (&vd0.x)[j];
            float fa1 = (&va1.x)[j], fb1 = (&vb1.x)[j], fc1 = (&vc1.x)[j], fd1 = (&vd1.x)[j];
            float fv0[5], fv1[5];
            fv0[0] = (&vx0.x)[j];
            fv0[1] = fabsf(fa0 - fc0);
            fv0[2] = fa0 + fc0;
            fv0[3] = fabsf(fb0 - fd0);
            fv0[4] = fb0 + fd0;
            fv1[0] = (&vx1.x)[j];
            fv1[1] = fabsf(fa1 - fc1);
            fv1[2] = fa1 + fc1;
            fv1[3] = fabsf(fb1 - fd1);
            fv1[4] = fb1 + fd1;
#pragma unroll
            for (int s = 0; s < 5; s++) {
                u64 f20 = splat2(fv0[s]);
                u64 f21 = splat2(fv1[s]);
                // this thread's 16 channels: 4 LDS.128 per cs
                const ulonglong2* wr =
                    (const ulonglong2*)&s_W[(c * 5 + s) * COUT + half * 16];
#pragma unroll
                for (int q = 0; q < 4; q++) {
                    ulonglong2 w2 = wr[q];
                    ffma2(acc0[2 * q],     f20, w2.x);
                    ffma2(acc0[2 * q + 1], f20, w2.y);
                    ffma2(acc1[2 * q],     f21, w2.x);
                    ffma2(acc1[2 * q + 1], f21, w2.y);
                }
            }
        }
    }

    // e even: float2 store covers edges e, e+1 for each owned channel.
    float* ob = out + (size_t)b * COUT * EDGES + e;
#pragma unroll
    for (int p = 0; p < 8; p++) {
        float l0, h0, l1, h1;
        unpack2(acc0[p], l0, h0);
        unpack2(acc1[p], l1, h1);
        int o = half * 16 + 2 * p;
        *(float2*)(ob + (size_t)o       * EDGES) = make_float2(l0, l1);
        *(float2*)(ob + (size_t)(o + 1) * EDGES) = make_float2(h0, h1);
    }
}

// ---------------------------------------------------------------------------
// Kernel 3: BN statistics. 4 chunk-blocks per (b, o) row (1024 blocks).
// ---------------------------------------------------------------------------
__global__ __launch_bounds__(256) void stats_kernel(const float* __restrict__ out) {
    __shared__ float s1[256];
    __shared__ float s2[256];
    int blk   = blockIdx.x;               // blk = (b*COUT + o) * 4 + chunk
    int row   = blk >> 2;
    int chunk = blk & 3;
    int o     = row & (COUT - 1);
    const int E4 = EDGES / 4;             // 30000 float4 per row
    const int C4 = E4 / 4;                // 7500 float4 per chunk
    const float4* rp = (const float4*)(out + (size_t)row * EDGES) + chunk * C4;

    float a1 = 0.f, a2 = 0.f;
    for (int j = threadIdx.x; j < C4; j += 256) {
        float4 v = rp[j];
        a1 += v.x + v.y + v.z + v.w;
        a2 += v.x * v.x + v.y * v.y + v.z * v.z + v.w * v.w;
    }
    s1[threadIdx.x] = a1;
    s2[threadIdx.x] = a2;
    __syncthreads();
#pragma unroll
    for (int st = 128; st > 0; st >>= 1) {
        if (threadIdx.x < st) {
            s1[threadIdx.x] += s1[threadIdx.x + st];
            s2[threadIdx.x] += s2[threadIdx.x + st];
        }
        __syncthreads();
    }
    if (threadIdx.x == 0) {
        atomicAdd(&g_sum[o],   s1[0]);
        atomicAdd(&g_sumsq[o], s2[0]);
    }
}

// ---------------------------------------------------------------------------
// Kernel 4: y -> relu(y*scale + shift), in place (finalize merged).
// ---------------------------------------------------------------------------
__global__ __launch_bounds__(256) void norm_relu_kernel(float* __restrict__ out,
                                                        const float* __restrict__ gamma,
                                                        const float* __restrict__ beta) {
    __shared__ float s_scale[COUT];
    __shared__ float s_shift[COUT];
    if (threadIdx.x < COUT) {
        int o = threadIdx.x;
        float inv  = 1.0f / (float)NTOT;
        float mean = g_sum[o] * inv;
        float var  = g_sumsq[o] * inv - mean * mean;
        float rstd = rsqrtf(var + BN_EPS);
        float sc   = gamma[o] * rstd;
        s_scale[o] = sc;
        s_shift[o] = beta[o] - mean * sc;
    }
    __syncthreads();

    int i = blockIdx.x * 256 + threadIdx.x;      // float4 index, exact grid
    const int E4 = EDGES / 4;
    int o = (i / E4) & (COUT - 1);
    float sc = s_scale[o];
    float sh = s_shift[o];
    float4 v = ((float4*)out)[i];
    v.x = fmaxf(fmaf(v.x, sc, sh), 0.f);
    v.y = fmaxf(fmaf(v.y, sc, sh), 0.f);
    v.z = fmaxf(fmaf(v.z, sc, sh), 0.f);
    v.w = fmaxf(fmaf(v.w, sc, sh), 0.f);
    ((float4*)out)[i] = v;
}

// ---------------------------------------------------------------------------
extern "C" void kernel_launch(void* const* d_in, const int* in_sizes, int n_in,
                              void* d_out, int out_size) {
    const float* x     = (const float*)d_in[0];
    const int*   gemm  = (const int*)  d_in[1];
    const float* W     = (const float*)d_in[2];
    const float* bias  = (const float*)d_in[3];
    const float* gamma = (const float*)d_in[4];
    const float* beta  = (const float*)d_in[5];
    float* out = (float*)d_out;

    transpose_kernel<<<NTOT / 256, 256>>>(x);
    conv_kernel<<<NTOT / 128, 128>>>(gemm, W, bias, out);   // 128 edges per block
    stats_kernel<<<B * COUT * 4, 256>>>(out);
    norm_relu_kernel<<<(NTOT * COUT / 4) / 256, 256>>>(out, gamma, beta);
}

// round 15
// speedup vs baseline: 1.6064x; 1.2592x over previous
#include <cuda_runtime.h>

#define B 8
#define CIN 16
#define COUT 32
#define EDGES 120000
#define NTOT (B * EDGES)            // 960000
#define BN_EPS 1e-5f

typedef unsigned long long u64;

// Scratch: transposed x [B*E, CIN] (61.4 MB) + BN stat accumulators.
__device__ float g_xT[(size_t)NTOT * CIN];
__device__ float g_sum[COUT];
__device__ float g_sumsq[COUT];

// Weights + bias in constant memory: weight reads go through the constant
// port (LDC/uniform path), off the smem crossbar and LSU queue entirely.
__constant__ __align__(16) float c_W[CIN * 5 * COUT];   // [c*5+s][o]
__constant__ __align__(16) float c_bias[COUT];

// ---- packed f32x2 helpers (sm_100+) ---------------------------------------
__device__ __forceinline__ u64 splat2(float f) {
    u64 r;
    asm("mov.b64 %0, {%1, %1};" : "=l"(r) : "f"(f));
    return r;
}
__device__ __forceinline__ void ffma2(u64& acc, u64 a, u64 b) {
    asm("fma.rn.f32x2 %0, %1, %2, %0;" : "+l"(acc) : "l"(a), "l"(b));
}
__device__ __forceinline__ void unpack2(u64 v, float& lo, float& hi) {
    asm("mov.b64 {%0, %1}, %2;" : "=f"(lo), "=f"(hi) : "l"(v));
}

// ---------------------------------------------------------------------------
// Kernel 0: repack W from [o][cs] to [cs][o] into a device staging buffer
// (then a D2D graph memcpy node lands it in c_W).
// ---------------------------------------------------------------------------
__device__ __align__(16) float g_Wt[CIN * 5 * COUT];
__global__ void repack_W_kernel(const float* __restrict__ W) {
    int j = threadIdx.x + blockIdx.x * 256;
    if (j < CIN * 5 * COUT) {
        int cs = j >> 5;
        int o  = j & 31;
        g_Wt[j] = W[o * (CIN * 5) + cs];
    }
}

// ---------------------------------------------------------------------------
// Kernel 1: transpose x [B, CIN, E] -> g_xT [B*E, CIN]; zero stat buffers.
// ---------------------------------------------------------------------------
__global__ __launch_bounds__(256) void transpose_kernel(const float* __restrict__ x) {
    int i = blockIdx.x * 256 + threadIdx.x;
    if (blockIdx.x == 0 && threadIdx.x < 2 * COUT) {
        if (threadIdx.x < COUT) g_sum[threadIdx.x] = 0.f;
        else                    g_sumsq[threadIdx.x - COUT] = 0.f;
    }
    if (i >= NTOT) return;
    int b = i / EDGES;
    int e = i - b * EDGES;
    const float* xb = x + (size_t)b * CIN * EDGES + e;
    float v[CIN];
#pragma unroll
    for (int c = 0; c < CIN; c++) v[c] = xb[(size_t)c * EDGES];
    float4* dst = (float4*)&g_xT[(size_t)i * CIN];
#pragma unroll
    for (int q = 0; q < 4; q++)
        dst[q] = make_float4(v[4 * q], v[4 * q + 1], v[4 * q + 2], v[4 * q + 3]);
}

// ---------------------------------------------------------------------------
// Kernel 2: mesh conv + bias -> d_out. FOUR consecutive edges per thread
// (identical blocking to the 239.6us best), but weights/bias read from
// CONSTANT memory -> no smem crossbar traffic for weights; LDC overlaps
// with gather LDG on a separate port.
// ---------------------------------------------------------------------------
__global__ __launch_bounds__(128, 2) void conv_kernel(const int* __restrict__ gemm,
                                                      float* __restrict__ out) {
    int tid = threadIdx.x;
    int t   = blockIdx.x * 128 + tid;        // quad index, grid exact
    int i0  = 4 * t;                         // first edge (multiple of 4)
    int b   = i0 / EDGES;                    // EDGES % 4 == 0 -> quad in one batch
    int e   = i0 - b * EDGES;
    size_t nb = (size_t)b * EDGES;

    int4 g[4];
#pragma unroll
    for (int k = 0; k < 4; k++) g[k] = ((const int4*)gemm)[i0 + k];

    const float4* px[4];
    const float4* pa[4];
    const float4* pb[4];
    const float4* pc[4];
    const float4* pd[4];
#pragma unroll
    for (int k = 0; k < 4; k++) {
        px[k] = (const float4*)&g_xT[(size_t)(i0 + k) * CIN];
        pa[k] = (const float4*)&g_xT[(nb + (size_t)g[k].x) * CIN];
        pb[k] = (const float4*)&g_xT[(nb + (size_t)g[k].y) * CIN];
        pc[k] = (const float4*)&g_xT[(nb + (size_t)g[k].z) * CIN];
        pd[k] = (const float4*)&g_xT[(nb + (size_t)g[k].w) * CIN];
    }

    // acc[k][p]: edge k, channel pair p (ch 2p, 2p+1), bias-initialized.
    u64 acc[4][COUT / 2];
    const u64* bias2 = (const u64*)c_bias;
#pragma unroll
    for (int k = 0; k < 4; k++)
#pragma unroll
        for (int p = 0; p < COUT / 2; p++) acc[k][p] = bias2[p];

#pragma unroll
    for (int cc = 0; cc < 4; cc++) {
        float4 vx[4], va[4], vb[4], vc[4], vd[4];
#pragma unroll
        for (int k = 0; k < 4; k++) {
            vx[k] = px[k][cc];
            va[k] = pa[k][cc];
            vb[k] = pb[k][cc];
            vc[k] = pc[k][cc];
            vd[k] = pd[k][cc];
        }
#pragma unroll
        for (int j = 0; j < 4; j++) {
            int c = cc * 4 + j;
            float fv[4][5];
#pragma unroll
            for (int k = 0; k < 4; k++) {
                float fx = (&vx[k].x)[j];
                float fa = (&va[k].x)[j];
                float fb = (&vb[k].x)[j];
                float fc = (&vc[k].x)[j];
                float fd = (&vd[k].x)[j];
                fv[k][0] = fx;
                fv[k][1] = fabsf(fa - fc);
                fv[k][2] = fa + fc;
                fv[k][3] = fabsf(fb - fd);
                fv[k][4] = fb + fd;
            }
#pragma unroll
            for (int s = 0; s < 5; s++) {
                u64 f2[4];
#pragma unroll
                for (int k = 0; k < 4; k++) f2[k] = splat2(fv[k][s]);
                const ulonglong2* wr = (const ulonglong2*)&c_W[(c * 5 + s) * COUT];
#pragma unroll
                for (int q = 0; q < 8; q++) {   // constant-port weight read
                    ulonglong2 w2 = wr[q];
#pragma unroll
                    for (int k = 0; k < 4; k++) {
                        ffma2(acc[k][2 * q],     f2[k], w2.x);
                        ffma2(acc[k][2 * q + 1], f2[k], w2.y);
                    }
                }
            }
        }
    }

    // e % 4 == 0: float4 store covers edges e..e+3 for each channel.
    float* ob = out + (size_t)b * COUT * EDGES + e;
#pragma unroll
    for (int p = 0; p < COUT / 2; p++) {
        float lo[4], hi[4];
#pragma unroll
        for (int k = 0; k < 4; k++) unpack2(acc[k][p], lo[k], hi[k]);
        *(float4*)(ob + (size_t)(2 * p)     * EDGES) = make_float4(lo[0], lo[1], lo[2], lo[3]);
        *(float4*)(ob + (size_t)(2 * p + 1) * EDGES) = make_float4(hi[0], hi[1], hi[2], hi[3]);
    }
}

// ---------------------------------------------------------------------------
// Kernel 3: BN statistics. 4 chunk-blocks per (b, o) row (1024 blocks).
// ---------------------------------------------------------------------------
__global__ __launch_bounds__(256) void stats_kernel(const float* __restrict__ out) {
    __shared__ float s1[256];
    __shared__ float s2[256];
    int blk   = blockIdx.x;               // blk = (b*COUT + o) * 4 + chunk
    int row   = blk >> 2;
    int chunk = blk & 3;
    int o     = row & (COUT - 1);
    const int E4 = EDGES / 4;             // 30000 float4 per row
    const int C4 = E4 / 4;                // 7500 float4 per chunk
    const float4* rp = (const float4*)(out + (size_t)row * EDGES) + chunk * C4;

    float a1 = 0.f, a2 = 0.f;
    for (int j = threadIdx.x; j < C4; j += 256) {
        float4 v = rp[j];
        a1 += v.x + v.y + v.z + v.w;
        a2 += v.x * v.x + v.y * v.y + v.z * v.z + v.w * v.w;
    }
    s1[threadIdx.x] = a1;
    s2[threadIdx.x] = a2;
    __syncthreads();
#pragma unroll
    for (int st = 128; st > 0; st >>= 1) {
        if (threadIdx.x < st) {
            s1[threadIdx.x] += s1[threadIdx.x + st];
            s2[threadIdx.x] += s2[threadIdx.x + st];
        }
        __syncthreads();
    }
    if (threadIdx.x == 0) {
        atomicAdd(&g_sum[o],   s1[0]);
        atomicAdd(&g_sumsq[o], s2[0]);
    }
}

// ---------------------------------------------------------------------------
// Kernel 4: y -> relu(y*scale + shift), in place (finalize merged).
// ---------------------------------------------------------------------------
__global__ __launch_bounds__(256) void norm_relu_kernel(float* __restrict__ out,
                                                        const float* __restrict__ gamma,
                                                        const float* __restrict__ beta) {
    __shared__ float s_scale[COUT];
    __shared__ float s_shift[COUT];
    if (threadIdx.x < COUT) {
        int o = threadIdx.x;
        float inv  = 1.0f / (float)NTOT;
        float mean = g_sum[o] * inv;
        float var  = g_sumsq[o] * inv - mean * mean;
        float rstd = rsqrtf(var + BN_EPS);
        float sc   = gamma[o] * rstd;
        s_scale[o] = sc;
        s_shift[o] = beta[o] - mean * sc;
    }
    __syncthreads();

    int i = blockIdx.x * 256 + threadIdx.x;      // float4 index, exact grid
    const int E4 = EDGES / 4;
    int o = (i / E4) & (COUT - 1);
    float sc = s_scale[o];
    float sh = s_shift[o];
    float4 v = ((float4*)out)[i];
    v.x = fmaxf(fmaf(v.x, sc, sh), 0.f);
    v.y = fmaxf(fmaf(v.y, sc, sh), 0.f);
    v.z = fmaxf(fmaf(v.z, sc, sh), 0.f);
    v.w = fmaxf(fmaf(v.w, sc, sh), 0.f);
    ((float4*)out)[i] = v;
}

// ---------------------------------------------------------------------------
extern "C" void kernel_launch(void* const* d_in, const int* in_sizes, int n_in,
                              void* d_out, int out_size) {
    const float* x     = (const float*)d_in[0];
    const int*   gemm  = (const int*)  d_in[1];
    const float* W     = (const float*)d_in[2];
    const float* bias  = (const float*)d_in[3];
    const float* gamma = (const float*)d_in[4];
    const float* beta  = (const float*)d_in[5];
    float* out = (float*)d_out;

    // Resolve REAL device addresses of the symbols (host-side query; capture-
    // safe, no allocation). R14 bug: passing __device__ symbol g_Wt directly
    // as a src pointer used the host shadow address -> c_W stayed zero.
    void *dW = nullptr, *dWt = nullptr, *dBias = nullptr;
    cudaGetSymbolAddress(&dW,    c_W);
    cudaGetSymbolAddress(&dWt,   g_Wt);
    cudaGetSymbolAddress(&dBias, c_bias);

    repack_W_kernel<<<(CIN * 5 * COUT + 255) / 256, 256>>>(W);
    cudaMemcpyAsync(dW, dWt, CIN * 5 * COUT * sizeof(float),
                    cudaMemcpyDeviceToDevice);
    cudaMemcpyAsync(dBias, (const void*)bias, COUT * sizeof(float),
                    cudaMemcpyDeviceToDevice);

    transpose_kernel<<<NTOT / 256, 256>>>(x);
    conv_kernel<<<NTOT / 4 / 128, 128>>>(gemm, out);
    stats_kernel<<<B * COUT * 4, 256>>>(out);
    norm_relu_kernel<<<(NTOT * COUT / 4) / 256, 256>>>(out, gamma, beta);
}

// round 16
// speedup vs baseline: 1.6802x; 1.0460x over previous
#include <cuda_runtime.h>

#define B 8
#define CIN 16
#define COUT 32
#define EDGES 120000
#define NTOT (B * EDGES)            // 960000
#define BN_EPS 1e-5f

typedef unsigned long long u64;

// Scratch: transposed x [B*E, CIN] (61.4 MB) + BN stat accumulators.
__device__ float g_xT[(size_t)NTOT * CIN];
__device__ float g_sum[COUT];
__device__ float g_sumsq[COUT];

// Weights + bias in constant memory (constant port; off the LSU/crossbar).
__constant__ __align__(16) float c_W[CIN * 5 * COUT];   // [c*5+s][o]
__constant__ __align__(16) float c_bias[COUT];

// ---- packed f32x2 helpers (sm_100+) ---------------------------------------
__device__ __forceinline__ u64 splat2(float f) {
    u64 r;
    asm("mov.b64 %0, {%1, %1};" : "=l"(r) : "f"(f));
    return r;
}
__device__ __forceinline__ void ffma2(u64& acc, u64 a, u64 b) {
    asm("fma.rn.f32x2 %0, %1, %2, %0;" : "+l"(acc) : "l"(a), "l"(b));
}
__device__ __forceinline__ void unpack2(u64 v, float& lo, float& hi) {
    asm("mov.b64 {%0, %1}, %2;" : "=f"(lo), "=f"(hi) : "l"(v));
}

// ---------------------------------------------------------------------------
// Kernel 0: repack W from [o][cs] to [cs][o] into a device staging buffer
// (then a D2D graph memcpy node lands it in c_W).
// ---------------------------------------------------------------------------
__device__ __align__(16) float g_Wt[CIN * 5 * COUT];
__global__ void repack_W_kernel(const float* __restrict__ W) {
    int j = threadIdx.x + blockIdx.x * 256;
    if (j < CIN * 5 * COUT) {
        int cs = j >> 5;
        int o  = j & 31;
        g_Wt[j] = W[o * (CIN * 5) + cs];
    }
}

// ---------------------------------------------------------------------------
// Kernel 1: transpose x [B, CIN, E] -> g_xT [B*E, CIN]; zero stat buffers.
// ---------------------------------------------------------------------------
__global__ __launch_bounds__(256) void transpose_kernel(const float* __restrict__ x) {
    int i = blockIdx.x * 256 + threadIdx.x;
    if (blockIdx.x == 0 && threadIdx.x < 2 * COUT) {
        if (threadIdx.x < COUT) g_sum[threadIdx.x] = 0.f;
        else                    g_sumsq[threadIdx.x - COUT] = 0.f;
    }
    if (i >= NTOT) return;
    int b = i / EDGES;
    int e = i - b * EDGES;
    const float* xb = x + (size_t)b * CIN * EDGES + e;
    float v[CIN];
#pragma unroll
    for (int c = 0; c < CIN; c++) v[c] = xb[(size_t)c * EDGES];
    float4* dst = (float4*)&g_xT[(size_t)i * CIN];
#pragma unroll
    for (int q = 0; q < 4; q++)
        dst[q] = make_float4(v[4 * q], v[4 * q + 1], v[4 * q + 2], v[4 * q + 3]);
}

// ---------------------------------------------------------------------------
// Kernel 2: mesh conv + bias -> d_out. TWO consecutive edges per thread,
// weights from CONSTANT memory. acc = 64 regs -> launch_bounds(128,4)
// -> 4 warps/SMSP so the FFMA2 pipe stays saturated across LDC/gather
// stalls (R15's lb(128,2) left it idle ~40% of the time).
// ---------------------------------------------------------------------------
__global__ __launch_bounds__(128, 4) void conv_kernel(const int* __restrict__ gemm,
                                                      float* __restrict__ out) {
    int tid = threadIdx.x;
    int t   = blockIdx.x * 128 + tid;        // pair index, grid exact
    int i0  = 2 * t;                         // first edge (even)
    int b   = i0 / EDGES;                    // EDGES even -> pair in one batch
    int e   = i0 - b * EDGES;
    size_t nb = (size_t)b * EDGES;

    int4 g0 = ((const int4*)gemm)[i0];
    int4 g1 = ((const int4*)gemm)[i0 + 1];
    const float4* x0 = (const float4*)&g_xT[(size_t)i0 * CIN];
    const float4* x1 = (const float4*)&g_xT[(size_t)(i0 + 1) * CIN];
    const float4* a0 = (const float4*)&g_xT[(nb + (size_t)g0.x) * CIN];
    const float4* b0 = (const float4*)&g_xT[(nb + (size_t)g0.y) * CIN];
    const float4* c0 = (const float4*)&g_xT[(nb + (size_t)g0.z) * CIN];
    const float4* d0 = (const float4*)&g_xT[(nb + (size_t)g0.w) * CIN];
    const float4* a1 = (const float4*)&g_xT[(nb + (size_t)g1.x) * CIN];
    const float4* b1 = (const float4*)&g_xT[(nb + (size_t)g1.y) * CIN];
    const float4* c1 = (const float4*)&g_xT[(nb + (size_t)g1.z) * CIN];
    const float4* d1 = (const float4*)&g_xT[(nb + (size_t)g1.w) * CIN];

    u64 acc0[COUT / 2], acc1[COUT / 2];
    const u64* bias2 = (const u64*)c_bias;
#pragma unroll
    for (int p = 0; p < COUT / 2; p++) { acc0[p] = bias2[p]; acc1[p] = bias2[p]; }

#pragma unroll
    for (int cc = 0; cc < 4; cc++) {
        float4 vx0 = x0[cc], va0 = a0[cc], vb0 = b0[cc], vc0 = c0[cc], vd0 = d0[cc];
        float4 vx1 = x1[cc], va1 = a1[cc], vb1 = b1[cc], vc1 = c1[cc], vd1 = d1[cc];
#pragma unroll
        for (int j = 0; j < 4; j++) {
            int c = cc * 4 + j;
            float fa0 = (&va0.x)[j], fb0 = (&vb0.x)[j], fc0 = (&vc0.x)[j], fd0 = (&vd0.x)[j];
            float fa1 = (&va1.x)[j], fb1 = (&vb1.x)[j], fc1 = (&vc1.x)[j], fd1 = (&vd1.x)[j];
            float fv0[5], fv1[5];
            fv0[0] = (&vx0.x)[j];
            fv0[1] = fabsf(fa0 - fc0);
            fv0[2] = fa0 + fc0;
            fv0[3] = fabsf(fb0 - fd0);
            fv0[4] = fb0 + fd0;
            fv1[0] = (&vx1.x)[j];
            fv1[1] = fabsf(fa1 - fc1);
            fv1[2] = fa1 + fc1;
            fv1[3] = fabsf(fb1 - fd1);
            fv1[4] = fb1 + fd1;
#pragma unroll
            for (int s = 0; s < 5; s++) {
                u64 f20 = splat2(fv0[s]);
                u64 f21 = splat2(fv1[s]);
                const ulonglong2* wr = (const ulonglong2*)&c_W[(c * 5 + s) * COUT];
#pragma unroll
                for (int q = 0; q < 8; q++) {   // constant-port weight read
                    ulonglong2 w2 = wr[q];
                    ffma2(acc0[2 * q],     f20, w2.x);
                    ffma2(acc0[2 * q + 1], f20, w2.y);
                    ffma2(acc1[2 * q],     f21, w2.x);
                    ffma2(acc1[2 * q + 1], f21, w2.y);
                }
            }
        }
    }

    // e even: float2 store covers edges e, e+1 for each channel.
    float* ob = out + (size_t)b * COUT * EDGES + e;
#pragma unroll
    for (int p = 0; p < COUT / 2; p++) {
        float l0, h0, l1, h1;
        unpack2(acc0[p], l0, h0);
        unpack2(acc1[p], l1, h1);
        *(float2*)(ob + (size_t)(2 * p)     * EDGES) = make_float2(l0, l1);
        *(float2*)(ob + (size_t)(2 * p + 1) * EDGES) = make_float2(h0, h1);
    }
}

// ---------------------------------------------------------------------------
// Kernel 3: BN statistics. 4 chunk-blocks per (b, o) row (1024 blocks).
// ---------------------------------------------------------------------------
__global__ __launch_bounds__(256) void stats_kernel(const float* __restrict__ out) {
    __shared__ float s1[256];
    __shared__ float s2[256];
    int blk   = blockIdx.x;               // blk = (b*COUT + o) * 4 + chunk
    int row   = blk >> 2;
    int chunk = blk & 3;
    int o     = row & (COUT - 1);
    const int E4 = EDGES / 4;             // 30000 float4 per row
    const int C4 = E4 / 4;                // 7500 float4 per chunk
    const float4* rp = (const float4*)(out + (size_t)row * EDGES) + chunk * C4;

    float a1 = 0.f, a2 = 0.f;
    for (int j = threadIdx.x; j < C4; j += 256) {
        float4 v = rp[j];
        a1 += v.x + v.y + v.z + v.w;
        a2 += v.x * v.x + v.y * v.y + v.z * v.z + v.w * v.w;
    }
    s1[threadIdx.x] = a1;
    s2[threadIdx.x] = a2;
    __syncthreads();
#pragma unroll
    for (int st = 128; st > 0; st >>= 1) {
        if (threadIdx.x < st) {
            s1[threadIdx.x] += s1[threadIdx.x + st];
            s2[threadIdx.x] += s2[threadIdx.x + st];
        }
        __syncthreads();
    }
    if (threadIdx.x == 0) {
        atomicAdd(&g_sum[o],   s1[0]);
        atomicAdd(&g_sumsq[o], s2[0]);
    }
}

// ---------------------------------------------------------------------------
// Kernel 4: y -> relu(y*scale + shift), in place (finalize merged).
// ---------------------------------------------------------------------------
__global__ __launch_bounds__(256) void norm_relu_kernel(float* __restrict__ out,
                                                        const float* __restrict__ gamma,
                                                        const float* __restrict__ beta) {
    __shared__ float s_scale[COUT];
    __shared__ float s_shift[COUT];
    if (threadIdx.x < COUT) {
        int o = threadIdx.x;
        float inv  = 1.0f / (float)NTOT;
        float mean = g_sum[o] * inv;
        float var  = g_sumsq[o] * inv - mean * mean;
        float rstd = rsqrtf(var + BN_EPS);
        float sc   = gamma[o] * rstd;
        s_scale[o] = sc;
        s_shift[o] = beta[o] - mean * sc;
    }
    __syncthreads();

    int i = blockIdx.x * 256 + threadIdx.x;      // float4 index, exact grid
    const int E4 = EDGES / 4;
    int o = (i / E4) & (COUT - 1);
    float sc = s_scale[o];
    float sh = s_shift[o];
    float4 v = ((float4*)out)[i];
    v.x = fmaxf(fmaf(v.x, sc, sh), 0.f);
    v.y = fmaxf(fmaf(v.y, sc, sh), 0.f);
    v.z = fmaxf(fmaf(v.z, sc, sh), 0.f);
    v.w = fmaxf(fmaf(v.w, sc, sh), 0.f);
    ((float4*)out)[i] = v;
}

// ---------------------------------------------------------------------------
extern "C" void kernel_launch(void* const* d_in, const int* in_sizes, int n_in,
                              void* d_out, int out_size) {
    const float* x     = (const float*)d_in[0];
    const int*   gemm  = (const int*)  d_in[1];
    const float* W     = (const float*)d_in[2];
    const float* bias  = (const float*)d_in[3];
    const float* gamma = (const float*)d_in[4];
    const float* beta  = (const float*)d_in[5];
    float* out = (float*)d_out;

    // Resolve real device addresses of the symbols (host-side query; capture-
    // safe, no allocation), then D2D memcpy nodes land weights in constant mem.
    void *dW = nullptr, *dWt = nullptr, *dBias = nullptr;
    cudaGetSymbolAddress(&dW,    c_W);
    cudaGetSymbolAddress(&dWt,   g_Wt);
    cudaGetSymbolAddress(&dBias, c_bias);

    repack_W_kernel<<<(CIN * 5 * COUT + 255) / 256, 256>>>(W);
    cudaMemcpyAsync(dW, dWt, CIN * 5 * COUT * sizeof(float),
                    cudaMemcpyDeviceToDevice);
    cudaMemcpyAsync(dBias, (const void*)bias, COUT * sizeof(float),
                    cudaMemcpyDeviceToDevice);

    transpose_kernel<<<NTOT / 256, 256>>>(x);
    conv_kernel<<<NTOT / 2 / 128, 128>>>(gemm, out);
    stats_kernel<<<B * COUT * 4, 256>>>(out);
    norm_relu_kernel<<<(NTOT * COUT / 4) / 256, 256>>>(out, gamma, beta);
}